// round 12
// baseline (speedup 1.0000x reference)
#include <cuda_runtime.h>
#include <cstdint>

// ----------------------------------------------------------------------------
// HashingDiscretizer — R12.
// Verified env: keys int32, output f32 concat [out_keys | out_vals] (2*nnz),
// feature_ids == arange(F) (runtime-verified; fallbacks kept).
// R12: direct-mapped per-feature cell table — ONE 1-byte gather resolves the
// bin for ~90% of calibrated elements. cell = clamp((int)((v+5)*204.8)),
// computed identically (forced RN intrinsics) at build and runtime, so the
// stored count/flag is exact by monotonicity. Flagged cells (boundary shares
// the cell) do an exact forward scan on the original f32 bins row.
// ----------------------------------------------------------------------------

static constexpr int  LUT_SIZE = 65536;
static constexpr int  NBIN     = 63;
static constexpr int  ROW      = 72;        // legacy btree (fallback paths)
static constexpr int  MAX_F    = 8192;
static constexpr int  NCELL    = 2048;
static constexpr unsigned GOLDEN = 0x9E3779B9u;
static constexpr unsigned OUT_MASK_U = 0x3FFFFFu;        // (1<<22)-1

__device__ int g_is64 = 0;
__device__ int g_not_arange = 0;  // monotone 0->1 via atomicOr (deterministic)
__device__ unsigned short g_lut[LUT_SIZE];               // fallback LUT
__device__ __align__(32) float g_btree[MAX_F * ROW];     // fallback btree
__device__ __align__(16) unsigned char g_cell[MAX_F * NCELL];  // 16MB

// Monotone quantizer shared by build + runtime (forced RN, no contraction).
__device__ __forceinline__ int cell_of(float v) {
    float t = __fmul_rn(__fadd_rn(v, 5.0f), 204.8f);
    int c = (int)t;                       // trunc-toward-zero, saturating
    return min(max(c, 0), NCELL - 1);
}

// ---- K1: fused probe + arange-check + LUT + legacy btree -------------------
__global__ void build_tables(const void* __restrict__ fids,
                             const float* __restrict__ bins,
                             int F, int force64) {
    int t = blockIdx.x * blockDim.x + threadIdx.x;

    const int* fw = (const int*)fids;
    const bool is64 = force64 || (fw[1] == 0 && fw[3] == 0);
    if (t == 0) g_is64 = is64 ? 1 : 0;

    const long long* f64p = (const long long*)fids;
    const int*       f32p = (const int*)fids;

    if (t < LUT_SIZE) {
        if (t < F) {
            long long fv = is64 ? f64p[t] : (long long)f32p[t];
            if (fv != (long long)t) atomicOr(&g_not_arange, 1);
        }
        long long key = (long long)t;
        int lo = 0, hi = F;
        while (lo < hi) {
            int mid = (lo + hi) >> 1;
            long long fv = is64 ? f64p[mid] : (long long)f32p[mid];
            if (fv < key) lo = mid + 1; else hi = mid;
        }
        int idx = lo < (F - 1) ? lo : (F - 1);
        long long fv = is64 ? f64p[idx] : (long long)f32p[idx];
        unsigned short v = (unsigned short)(idx & 0x7FFF);
        if (fv == key) v |= 0x8000u;
        g_lut[t] = v;
    }
    if (t < F * ROW) {                    // legacy btree for fallback paths
        int f = t / ROW;
        int j = t - f * ROW;
        const float INF = __int_as_float(0x7f800000);
        float v;
        if (j < 8) {
            v = (j < 7) ? __ldg(&bins[f * NBIN + 8 * j + 7]) : INF;
        } else {
            int q = j - 8, l = q >> 3, p = q & 7;
            v = (p < 7) ? __ldg(&bins[f * NBIN + 8 * l + p]) : INF;
        }
        g_btree[t] = v;
    }
}

// ---- K2: cell table build — one warp per feature ---------------------------
__global__ void __launch_bounds__(256)
build_cells(const float* __restrict__ bins, int F) {
    __shared__ int cbs[8][64];            // 8 warps/block, 63 cells + pad
    int wid  = threadIdx.x >> 5;
    int lane = threadIdx.x & 31;
    int f = blockIdx.x * 8 + wid;
    if (f >= F) return;

    // cell index of each boundary (sorted ascending since bins row sorted
    // and cell_of is monotone nondecreasing)
    if (lane < 32) {
        if (lane < NBIN)      cbs[wid][lane]      = cell_of(__ldg(&bins[f * NBIN + lane]));
        if (lane + 32 < NBIN) cbs[wid][lane + 32] = cell_of(__ldg(&bins[f * NBIN + lane + 32]));
    }
    __syncwarp();

    // each lane fills 64 consecutive cells via merge walk
    const int c0 = lane * 64;
    int idx = 0;
    while (idx < NBIN && cbs[wid][idx] < c0) idx++;
    unsigned char outb[64];
    #pragma unroll 16
    for (int i = 0; i < 64; i++) {
        int c = c0 + i;
        while (idx < NBIN && cbs[wid][idx] < c) idx++;
        bool flag = (idx < NBIN) && (cbs[wid][idx] == c);
        outb[i] = (unsigned char)(idx | (flag ? 0x80 : 0));
    }
    uint4* dst = (uint4*)(g_cell + (size_t)f * NCELL + c0);
    const uint4* src = (const uint4*)outb;
    dst[0] = src[0]; dst[1] = src[1]; dst[2] = src[2]; dst[3] = src[3];
}

// ---- generic per-element path (fallback configs + tails) -------------------
template <bool AR>
__device__ __forceinline__ void process_one(long long k, float v, int F,
                                            unsigned& okey, float& oval) {
    unsigned long long u = (unsigned long long)k;
    bool cal; int idx;
    if (AR) { cal = u < (unsigned long long)F; idx = (int)u; }
    else {
        if (u < (unsigned long long)LUT_SIZE) {
            unsigned short e = g_lut[u];
            cal = (e & 0x8000u) != 0; idx = (int)(e & 0x7FFFu);
        } else { cal = false; idx = 0; }
    }
    if (cal) {
        const float* nb = g_btree + idx * ROW;
        float4 s0 = *(const float4*)(nb);
        float4 s1 = *(const float4*)(nb + 4);
        int c = (s0.x < v) + (s0.y < v) + (s0.z < v) + (s0.w < v)
              + (s1.x < v) + (s1.y < v) + (s1.z < v) + (s1.w < v);
        const float* lf = nb + 8 + c * 8;
        float4 l0 = *(const float4*)(lf);
        float4 l1 = *(const float4*)(lf + 4);
        int bin = c * 8
              + (l0.x < v) + (l0.y < v) + (l0.z < v) + (l0.w < v)
              + (l1.x < v) + (l1.y < v) + (l1.z < v) + (l1.w < v);
        unsigned h = ((unsigned)u * GOLDEN + (unsigned)bin) * GOLDEN;
        okey = h & OUT_MASK_U; oval = 1.0f;
    } else {
        okey = (unsigned)(u & (unsigned long long)OUT_MASK_U);
        oval = v;
    }
}

// ---- main kernel ------------------------------------------------------------
__global__ void __launch_bounds__(256)
hashing_discretizer_kernel(const void* __restrict__ keysv,
                           const float* __restrict__ valsv,
                           const float* __restrict__ bins,
                           int nnz, void* __restrict__ outv, int F) {
    const bool is64 = (g_is64 != 0);
    const bool ar   = (g_not_arange == 0);

    if (!is64 && ar) {
        const int*   keys = (const int*)keysv;
        const float* vals = valsv;
        float*       out  = (float*)outv;

        int t = blockIdx.x * blockDim.x + threadIdx.x;
        int i0 = t * 4;
        if (i0 >= nnz) return;

        if (i0 + 3 < nnz) {
            int4   kk = __ldcs((const int4*)(keys + i0));
            float4 vv = __ldcs((const float4*)(vals + i0));
            unsigned u[4] = {(unsigned)kk.x, (unsigned)kk.y,
                             (unsigned)kk.z, (unsigned)kk.w};
            float v[4] = {vv.x, vv.y, vv.z, vv.w};

            // batched independent byte gathers (one per calibrated element)
            unsigned char byte[4];
            #pragma unroll
            for (int j = 0; j < 4; j++) {
                byte[j] = 0;
                if (u[j] < (unsigned)F)
                    byte[j] = __ldg(&g_cell[(size_t)u[j] * NCELL + cell_of(v[j])]);
            }

            float ok[4], ov[4];
            #pragma unroll
            for (int j = 0; j < 4; j++) {
                if (u[j] < (unsigned)F) {
                    int bin = byte[j] & 0x7F;
                    if (byte[j] & 0x80) {          // rare exact forward scan
                        const float* row = bins + (size_t)u[j] * NBIN;
                        float vj = v[j];
                        while (bin < NBIN && __ldg(&row[bin]) < vj) bin++;
                    }
                    unsigned h = (u[j] * GOLDEN + (unsigned)bin) * GOLDEN;
                    ok[j] = (float)(h & OUT_MASK_U);
                    ov[j] = 1.0f;
                } else {
                    ok[j] = (float)(u[j] & OUT_MASK_U);
                    ov[j] = v[j];
                }
            }
            __stcs((float4*)(out + i0),
                   make_float4(ok[0], ok[1], ok[2], ok[3]));
            __stcs((float4*)(out + nnz + i0),
                   make_float4(ov[0], ov[1], ov[2], ov[3]));
        } else {
            for (int i = i0; i < nnz; i++) {
                unsigned ok; float ov;
                process_one<true>((long long)keys[i], vals[i], F, ok, ov);
                out[i] = (float)ok;
                out[nnz + i] = ov;
            }
        }
    } else {
        // fallback configs: scalar, 4 elems/thread
        int t = blockIdx.x * blockDim.x + threadIdx.x;
        long long i0 = (long long)t * 4;
        long long total = nnz;
        if (i0 >= total) return;
        long long iend = (i0 + 4 < total) ? i0 + 4 : total;
        for (long long i = i0; i < iend; i++) {
            long long k = is64 ? ((const long long*)keysv)[i]
                               : (long long)((const int*)keysv)[i];
            unsigned okk; float ovv;
            if (ar) process_one<true >(k, valsv[i], F, okk, ovv);
            else    process_one<false>(k, valsv[i], F, okk, ovv);
            if (is64) {
                double* o = (double*)outv;
                o[i] = (double)okk; o[total + i] = (double)ovv;
            } else {
                float* o = (float*)outv;
                o[i] = (float)okk;  o[total + i] = ovv;
            }
        }
    }
}

extern "C" void kernel_launch(void* const* d_in, const int* in_sizes, int n_in,
                              void* d_out, int out_size) {
    // ---- classify inputs by element count (order-agnostic) ----
    long long s[16];
    int n = n_in < 16 ? n_in : 16;
    for (int i = 0; i < n; i++) s[i] = (long long)in_sizes[i];

    long long m1 = -1, m2 = -1;
    for (int i = 0; i < n; i++) {
        if (s[i] > m1) { m2 = m1; m1 = s[i]; }
        else if (s[i] > m2) { m2 = s[i]; }
    }

    int ik = -1, iv = -1;
    long long nnz_ll;
    int force64 = 0;
    if (m1 == m2) {
        for (int i = 0; i < n; i++)
            if (s[i] == m1) { if (ik < 0) ik = i; else if (iv < 0) iv = i; }
        nnz_ll = m1;
    } else {
        for (int i = 0; i < n; i++) {
            if (s[i] == m1 && ik < 0) ik = i;
            else if (s[i] == m1 / 2 && iv < 0) iv = i;
        }
        nnz_ll = m1 / 2;
        force64 = 1;
    }
    if (iv < 0) iv = ik;

    int ia = -1, ib = -1;
    for (int i = 0; i < n; i++) {
        if (i == ik || i == iv) continue;
        if (ia < 0) ia = i; else if (ib < 0) ib = i;
    }
    if (ib < 0) ib = ia;
    int iF = (s[ia] <= s[ib]) ? ia : ib;   // feature_ids (smaller)
    int iB = (iF == ia) ? ib : ia;         // bin_vals

    int nnz = (int)nnz_ll;
    int F = (int)(force64 ? s[iF] / 2 : s[iF]);
    if (F > MAX_F) F = MAX_F;
    if (F < 1) F = 1;

    const void*  keys = d_in[ik];
    const float* vals = (const float*)d_in[iv];
    const void*  fids = d_in[iF];
    const float* bins = (const float*)d_in[iB];

    int build_n = F * ROW;
    if (build_n < LUT_SIZE) build_n = LUT_SIZE;
    build_tables<<<(build_n + 255) / 256, 256>>>(fids, bins, F, force64);
    build_cells<<<(F + 7) / 8, 256>>>(bins, F);

    int nthreads = (nnz + 3) / 4;
    hashing_discretizer_kernel<<<(nthreads + 255) / 256, 256>>>(
        keys, vals, bins, nnz, d_out, F);
}